// round 10
// baseline (speedup 1.0000x reference)
#include <cuda_runtime.h>
#include <math.h>
#include <stdint.h>

#define BB 4
#define CC 256
#define HH 64
#define WW 128
#define HW (HH*WW)           // 8192
#define HID 128
#define IN_DIM 596
#define ICP1 608             // conv1 K-channels padded to /32
#define NCH1 19
#define NCH2 4
#define GROUPS 8
#define CPG (HID/GROUPS)     // 16

#define HP 66                // padded height (conv layout)
#define WP 130               // padded width  (conv layout)
#define NP (HP*WP)           // 8580 padded pixels
#define SLACK 512            // float slack both ends (B super-strip over-read)

#define BH 72                // corr-padded height (+-4)
#define BW 136               // corr-padded width  (+-4)
#define NB (BH*BW)           // 9792

#define TQ 256               // conv CTA N-tile (q pixels)
#define NTILES 34            // ceil(8580/256)
#define BST 520              // B super-strip stride (>=519, ==8 mod 32, 16B-mult)
#define AFSZ 5120            // packed A floats per (ch,tap): 4k8 * 2wm * 32lane * 20

// ---------------- scratch (device globals; zero-initialized) ----------------------
__device__ float g_xp_raw [(size_t)BB*ICP1*NP + 2*SLACK];  // padded conv1 input
__device__ float g_h1a_raw[(size_t)BB*HID *NP + 2*SLACK];  // padded conv2 input
__device__ float g_bwp [(size_t)BB*CC*NB];   // warped feat_b, 4-px zero pad (fp32)
__device__ float g_invna[BB*HW];
__device__ float g_invnbp[BB*NB];
__device__ float g_cp  [(size_t)2*BB*81*HW]; // corr partial sums (2 K-groups)
__device__ float g_h1 [(size_t)BB*HID*HW];
__device__ float g_h2 [(size_t)BB*HID*HW];
__device__ float g_h2a[(size_t)BB*HID*HW];
__device__ float g_gnm[BB*GROUPS];
__device__ float g_gnr[BB*GROUPS];
__device__ double g_gnp[BB*GROUPS*8][2];
__device__ float g_wA1[(size_t)NCH1*9*AFSZ];  // fragment-packed conv1 weights
__device__ float g_wA2[(size_t)NCH2*9*AFSZ];

__device__ __forceinline__ float tf32r(float x) {
    uint32_t u;
    asm("cvt.rna.tf32.f32 %0, %1;" : "=r"(u) : "f"(x));
    return __uint_as_float(u);
}
__device__ __forceinline__ uint32_t s2u(const void* p) {
    return (uint32_t)__cvta_generic_to_shared(p);
}
__device__ __forceinline__ void cpa16(uint32_t s, const void* g) {
    asm volatile("cp.async.cg.shared.global [%0], [%1], 16;" :: "r"(s), "l"(g));
}
#define CP_COMMIT() asm volatile("cp.async.commit_group;" ::: "memory")
#define CP_WAIT0()  asm volatile("cp.async.wait_group 0;" ::: "memory")
#define CP_WAIT1()  asm volatile("cp.async.wait_group 1;" ::: "memory")

// ---------------- 0. weight prep: fragment-packed layout --------------------------
__global__ void prep_w_kernel(const float* __restrict__ w1,
                              const float* __restrict__ w2) {
    int i = blockIdx.x*blockDim.x + threadIdx.x;
    if (i < NCH1*9*AFSZ) {
        int bi = i / AFSZ, r = i % AFSZ;
        int t = r % 20, s = r / 20;
        int lane = s & 31, wmk = s >> 5;
        int wm = wmk & 1, k8 = wmk >> 1;
        float v = 0.f;
        if (t < 16) {
            int mt = t >> 2, j = t & 3;
            int tig = lane & 3, g = lane >> 2;
            int k  = k8*8 + tig + (j >> 1)*4;
            int oc = wm*64 + mt*16 + g + (j & 1)*8;
            int ch = bi / 9, tap = bi % 9;
            int ic = ch*32 + k;
            if (ic < IN_DIM) v = tf32r(w1[((size_t)oc*IN_DIM + ic)*9 + tap]);
        }
        g_wA1[i] = v;
    }
    if (i < NCH2*9*AFSZ) {
        int bi = i / AFSZ, r = i % AFSZ;
        int t = r % 20, s = r / 20;
        int lane = s & 31, wmk = s >> 5;
        int wm = wmk & 1, k8 = wmk >> 1;
        float v = 0.f;
        if (t < 16) {
            int mt = t >> 2, j = t & 3;
            int tig = lane & 3, g = lane >> 2;
            int k  = k8*8 + tig + (j >> 1)*4;
            int oc = wm*64 + mt*16 + g + (j & 1)*8;
            int ch = bi / 9, tap = bi % 9;
            int ic = ch*32 + k;
            v = tf32r(w2[((size_t)oc*HID + ic)*9 + tap]);
        }
        g_wA2[i] = v;
    }
}

// ---------------- 1. warp + concat fill + norms -----------------------------------
__global__ void fill_warp_kernel(const float* __restrict__ fa,
                                 const float* __restrict__ fb,
                                 const float* __restrict__ pf,
                                 const float* __restrict__ cm,
                                 float* __restrict__ xp) {
    __shared__ float sha[4][64], shb[4][64];
    int tid = threadIdx.x;
    int pxl = tid & 63, ck = tid >> 6;
    int gp = blockIdx.x*64 + pxl;
    int b = gp / HW, p = gp % HW;
    int y = p / WW, x = p % WW;
    int pq = (y+1)*WP + (x+1);
    int bq = (y+4)*BW + (x+4);

    float fx = pf[((size_t)(b*2+0))*HW + p];
    float fy = pf[((size_t)(b*2+1))*HW + p];
    float px = (float)x + fx;
    float py = (float)y + fy;
    float x0f = floorf(px), y0f = floorf(py);
    float wx = px - x0f,    wy = py - y0f;
    int x0 = (int)x0f, y0 = (int)y0f;
    int x1 = x0 + 1,   y1 = y0 + 1;
    float vx0 = (x0 >= 0 && x0 < WW) ? 1.f : 0.f;
    float vx1 = (x1 >= 0 && x1 < WW) ? 1.f : 0.f;
    float vy0 = (y0 >= 0 && y0 < HH) ? 1.f : 0.f;
    float vy1 = (y1 >= 0 && y1 < HH) ? 1.f : 0.f;
    int xc0 = min(max(x0,0),WW-1), xc1 = min(max(x1,0),WW-1);
    int yc0 = min(max(y0,0),HH-1), yc1 = min(max(y1,0),HH-1);
    float w00 = (1.f-wx)*(1.f-wy) * vx0*vy0;
    float w01 = wx*(1.f-wy)       * vx1*vy0;
    float w10 = (1.f-wx)*wy       * vx0*vy1;
    float w11 = wx*wy             * vx1*vy1;
    int i00 = yc0*WW + xc0, i01 = yc0*WW + xc1;
    int i10 = yc1*WW + xc0, i11 = yc1*WW + xc1;

    float sa = 0.f, sb = 0.f;
    float* xb = xp + (size_t)b*ICP1*NP;
    float* bw = g_bwp + (size_t)b*CC*NB;
    int c0 = ck*64;
    #pragma unroll 4
    for (int c = c0; c < c0+64; c++) {
        float a = fa[((size_t)(b*CC+c))*HW + p];
        xb[(size_t)c*NP + pq] = tf32r(a);
        sa += a*a;
        const float* fbp = fb + ((size_t)(b*CC+c))*HW;
        float wv = fbp[i00]*w00 + fbp[i01]*w01 + fbp[i10]*w10 + fbp[i11]*w11;
        xb[(size_t)(CC+c)*NP + pq] = tf32r(wv);
        bw[(size_t)c*NB + bq] = wv;
        sb += wv*wv;
    }
    sha[ck][pxl] = sa; shb[ck][pxl] = sb;
    __syncthreads();
    if (ck == 0) {
        float ta = sha[0][pxl]+sha[1][pxl]+sha[2][pxl]+sha[3][pxl];
        float tb = shb[0][pxl]+shb[1][pxl]+shb[2][pxl]+shb[3][pxl];
        g_invna[gp] = 1.f / fmaxf(sqrtf(ta), 1e-12f);
        g_invnbp[(size_t)b*NB + bq] = 1.f / fmaxf(sqrtf(tb), 1e-12f);
        xb[(size_t)512*NP + pq] = tf32r(fx);
        xb[(size_t)513*NP + pq] = tf32r(fy);
        xb[(size_t)514*NP + pq] = tf32r(cm[(size_t)b*HW + p]);
    }
}

// ---------------- 2a. corr partial: 2-row y-band, 2-way K-split -------------------
// grid (HH/2, BB, 2), block (32,9). Each CTA: 2 output rows, 128 channels (kg).
// Partial raw sums (unscaled) -> g_cp[kg][b][dyi*9+d][HW].
__global__ __launch_bounds__(288, 2)
void corr_part_kernel(const float* __restrict__ fa) {
    extern __shared__ float cs[];
    float* sa = cs;                 // [2][8][128]
    float* sb = cs + 2*8*128;       // [10][8][136]
    int y0 = blockIdx.x*2, b = blockIdx.y, kg = blockIdx.z;
    int xg = threadIdx.x, dyi = threadIdx.y;
    int tid = dyi*32 + xg;
    int xb0 = xg*4;

    float acc[2][4][9];
    #pragma unroll
    for (int yy = 0; yy < 2; yy++)
        #pragma unroll
        for (int j = 0; j < 4; j++)
            #pragma unroll
            for (int d = 0; d < 9; d++) acc[yy][j][d] = 0.f;

    for (int cc = 0; cc < 16; cc++) {
        int ic0 = kg*128 + cc*8;
        // sa: 2 rows x 8 ch x 32 f4 = 512 f4
        for (int e = tid; e < 512; e += 288) {
            int row = e >> 8, c = (e >> 5) & 7, f4 = e & 31;
            *(float4*)&sa[(row*8 + c)*128 + f4*4] =
                *(const float4*)(fa + ((size_t)(b*CC + ic0 + c))*HW + (size_t)(y0+row)*WW + f4*4);
        }
        // sb: 10 padded rows x 8 ch x 34 f4 = 2720 f4
        for (int e = tid; e < 2720; e += 288) {
            int row = e / 272, rem = e - row*272;
            int c = rem / 34, f4 = rem - c*34;
            *(float4*)&sb[(row*8 + c)*136 + f4*4] =
                *(const float4*)(g_bwp + ((size_t)(b*CC + ic0 + c))*NB + (size_t)(y0+row)*BW + f4*4);
        }
        __syncthreads();
        #pragma unroll
        for (int c = 0; c < 8; c++) {
            #pragma unroll
            for (int yy = 0; yy < 2; yy++) {
                float4 a4 = *(const float4*)&sa[(yy*8 + c)*128 + xb0];
                float av[4] = {a4.x, a4.y, a4.z, a4.w};
                const float* br = &sb[((yy+dyi)*8 + c)*136 + xb0];
                float4 b0 = *(const float4*)&br[0];
                float4 b1 = *(const float4*)&br[4];
                float4 b2 = *(const float4*)&br[8];
                float bv[12] = {b0.x,b0.y,b0.z,b0.w, b1.x,b1.y,b1.z,b1.w, b2.x,b2.y,b2.z,b2.w};
                #pragma unroll
                for (int j = 0; j < 4; j++)
                    #pragma unroll
                    for (int d = 0; d < 9; d++)
                        acc[yy][j][d] += av[j] * bv[j+d];
            }
        }
        __syncthreads();
    }
    #pragma unroll
    for (int yy = 0; yy < 2; yy++)
        #pragma unroll
        for (int d = 0; d < 9; d++) {
            float* o = &g_cp[(((size_t)kg*BB + b)*81 + dyi*9 + d)*HW + (size_t)(y0+yy)*WW + xb0];
            *(float4*)o = make_float4(acc[yy][0][d], acc[yy][1][d], acc[yy][2][d], acc[yy][3][d]);
        }
}

// ---------------- 2b. corr combine: sum partials, scale by norms, write xp --------
__global__ void corr_combine_kernel(float* __restrict__ xp) {
    int idx = blockIdx.x*blockDim.x + threadIdx.x;
    if (idx >= BB*81*HW) return;
    int p = idx & (HW-1);
    int j = (idx >> 13) % 81;
    int b = idx / (81*HW);
    int y = p >> 7, x = p & 127;
    int dyi = j / 9, d = j - dyi*9;
    float s = g_cp[(((size_t)0*BB + b)*81 + j)*HW + p]
            + g_cp[(((size_t)1*BB + b)*81 + j)*HW + p];
    float scale = g_invna[(size_t)b*HW + p]
                * g_invnbp[(size_t)b*NB + (size_t)(y+dyi)*BW + (x+d)];
    int ch = 515 + (8 - dyi)*9 + (8 - d);
    xp[((size_t)(b*ICP1 + ch))*NP + (size_t)(y+1)*WP + (x+1)] = tf32r(s * scale);
}

// ---------------- 3. conv3x3 tf32 mma GEMM, A+B double-buffered -------------------
__global__ __launch_bounds__(256, 1)
void conv_mma_kernel(const float* __restrict__ xp,
                     const float* __restrict__ wA,
                     const float* __restrict__ bias,
                     float* __restrict__ out,
                     int ICp, int nChunks) {
    extern __shared__ float smem[];
    float* Bs0 = smem;                     // 32*520
    float* Bs1 = smem + 32*BST;
    float* As0 = smem + 2*32*BST;          // AFSZ
    float* As1 = As0 + AFSZ;

    int tid  = threadIdx.x;
    int warp = tid >> 5, lane = tid & 31;
    int g = lane >> 2, tig = lane & 3;
    int wm = warp & 1;
    int n0 = (warp >> 1) * 64;
    int q0 = blockIdx.x * TQ;
    int b  = blockIdx.z;

    float acc[4][8][4];
    #pragma unroll
    for (int mt = 0; mt < 4; mt++)
        #pragma unroll
        for (int nt = 0; nt < 8; nt++)
            #pragma unroll
            for (int i = 0; i < 4; i++) acc[mt][nt][i] = 0.f;

    const float* xpb = xp + (size_t)b*ICp*NP + q0 - 132;
    uint32_t asU[2] = {s2u(As0), s2u(As1)};
    uint32_t bsU[2] = {s2u(Bs0), s2u(Bs1)};

    auto stageB = [&](int s, int ch) {
        const float* src = xpb + (size_t)ch*32*NP;
        #pragma unroll
        for (int r = 0; r < 17; r++) {
            int e = tid + r*256;
            if (e < 32*(BST/4)) {
                int k = e / (BST/4), n4 = e - k*(BST/4);
                cpa16(bsU[s] + (uint32_t)(k*BST + n4*4)*4, src + (size_t)k*NP + n4*4);
            }
        }
    };
    auto stageA = [&](int s, int ch, int tap) {
        const float* src = wA + ((size_t)ch*9 + tap)*AFSZ;
        #pragma unroll
        for (int r = 0; r < 5; r++) {
            int e = tid + r*256;
            cpa16(asU[s] + (uint32_t)(e << 4), src + (e << 2));
        }
    };

    stageB(0, 0);
    stageA(0, 0, 0);
    CP_COMMIT();
    CP_WAIT0();
    __syncthreads();

    float* Acur = As0; float* Anxt = As1;
    float* Bcur = Bs0; float* Bnxt = Bs1;
    int aCurIsd0 = 1, bCurIs0 = 1;

    for (int ch = 0; ch < nChunks; ch++) {
        bool moreCh = (ch + 1 < nChunks);
        for (int tap = 0; tap < 9; tap++) {
            bool lastAll = !moreCh && (tap == 8);
            bool bStageTap = (tap == 7) && moreCh;
            if (!lastAll) {
                int ntap = (tap == 8) ? 0 : tap + 1;
                int nch  = (tap == 8) ? ch + 1 : ch;
                stageA(aCurIsd0 ? 1 : 0, nch, ntap);
                CP_COMMIT();
                if (bStageTap) {
                    stageB(bCurIs0 ? 1 : 0, ch + 1);
                    CP_COMMIT();
                }
            }
            int ky = tap / 3, kx = tap - ky*3;
            int boff = 132 + (ky-1)*WP + (kx-1);
            #pragma unroll
            for (int k8 = 0; k8 < 4; k8++) {
                int kb = k8*8;
                const float4* Ab = (const float4*)&Acur[(((k8<<1) | wm)*32 + lane)*20];
                uint32_t af[4][4];
                #pragma unroll
                for (int mt = 0; mt < 4; mt++) {
                    float4 av = Ab[mt];
                    af[mt][0] = __float_as_uint(av.x);
                    af[mt][1] = __float_as_uint(av.y);
                    af[mt][2] = __float_as_uint(av.z);
                    af[mt][3] = __float_as_uint(av.w);
                }
                const float* B0 = &Bcur[(kb+tig)*BST + boff];
                const float* B4 = B0 + 4*BST;
                #pragma unroll
                for (int nt = 0; nt < 8; nt++) {
                    int n = n0 + nt*8 + g;
                    uint32_t b0 = __float_as_uint(B0[n]);
                    uint32_t b1 = __float_as_uint(B4[n]);
                    #pragma unroll
                    for (int mt = 0; mt < 4; mt++) {
                        float* d = acc[mt][nt];
                        asm volatile(
                            "mma.sync.aligned.m16n8k8.row.col.f32.tf32.tf32.f32 "
                            "{%0,%1,%2,%3},{%4,%5,%6,%7},{%8,%9},{%0,%1,%2,%3};"
                            : "+f"(d[0]), "+f"(d[1]), "+f"(d[2]), "+f"(d[3])
                            : "r"(af[mt][0]), "r"(af[mt][1]), "r"(af[mt][2]), "r"(af[mt][3]),
                              "r"(b0), "r"(b1));
                    }
                }
            }
            if (!lastAll) {
                if (bStageTap) CP_WAIT1(); else CP_WAIT0();
                __syncthreads();
                { float* t = Acur; Acur = Anxt; Anxt = t; aCurIsd0 ^= 1; }
                if (tap == 8) { float* t = Bcur; Bcur = Bnxt; Bnxt = t; bCurIs0 ^= 1; }
            }
        }
    }

    // epilogue
    #pragma unroll
    for (int mt = 0; mt < 4; mt++) {
        int ocA = wm*64 + mt*16 + g;
        int ocB = ocA + 8;
        float bvA = bias[ocA], bvB = bias[ocB];
        float* outA = out + ((size_t)(b*HID + ocA))*HW;
        float* outB = out + ((size_t)(b*HID + ocB))*HW;
        #pragma unroll
        for (int nt = 0; nt < 8; nt++) {
            int qb = q0 + n0 + nt*8 + tig*2;
            #pragma unroll
            for (int h = 0; h < 2; h++) {
                int q = qb + h;
                int yp = q / WP, xpx = q - yp*WP;
                if (yp >= 1 && yp <= HH && xpx >= 1 && xpx <= WW) {
                    int po = (yp-1)*WW + (xpx-1);
                    outA[po] = acc[mt][nt][h]   + bvA;
                    outB[po] = acc[mt][nt][2+h] + bvB;
                }
            }
        }
    }
}

// ---------------- 4. GroupNorm stats ----------------------------------------------
__global__ void gn_stats_part(const float* __restrict__ src) {
    int bg = blockIdx.x >> 3, part = blockIdx.x & 7;
    const float* p = src + (size_t)bg*CPG*HW + (size_t)part*(CPG*HW/8);
    const int n = CPG*HW/8;
    double s = 0.0, s2 = 0.0;
    for (int i = threadIdx.x; i < n; i += 256) {
        float v = p[i];
        s += v; s2 += (double)v*v;
    }
    __shared__ double sh[256], sh2[256];
    sh[threadIdx.x] = s; sh2[threadIdx.x] = s2;
    __syncthreads();
    for (int st = 128; st > 0; st >>= 1) {
        if (threadIdx.x < st) {
            sh[threadIdx.x]  += sh[threadIdx.x+st];
            sh2[threadIdx.x] += sh2[threadIdx.x+st];
        }
        __syncthreads();
    }
    if (threadIdx.x == 0) {
        g_gnp[blockIdx.x][0] = sh[0];
        g_gnp[blockIdx.x][1] = sh2[0];
    }
}
__global__ void gn_stats_fin() {
    int bg = threadIdx.x;
    if (bg >= BB*GROUPS) return;
    double s = 0.0, s2 = 0.0;
    for (int i = 0; i < 8; i++) { s += g_gnp[bg*8+i][0]; s2 += g_gnp[bg*8+i][1]; }
    const double n = (double)(CPG*HW);
    double m = s / n;
    double var = s2 / n - m*m;
    g_gnm[bg] = (float)m;
    g_gnr[bg] = rsqrtf((float)var + 1e-5f);
}

// ---------------- 5. GroupNorm apply + exact GELU ---------------------------------
__global__ void gn_apply_gelu_kernel(const float* __restrict__ src,
                                     const float* __restrict__ sc,
                                     const float* __restrict__ bi,
                                     float* __restrict__ dst,
                                     int padded) {
    int idx = blockIdx.x*blockDim.x + threadIdx.x;
    if (idx >= BB*HID*HW) return;
    int p = idx % HW;
    int c = (idx / HW) % HID;
    int b = idx / (HID*HW);
    int bg = b*GROUPS + c/CPG;
    float v = (src[idx] - g_gnm[bg]) * g_gnr[bg] * sc[c] + bi[c];
    float gl = 0.5f * v * (1.f + erff(v * 0.70710678118654752f));
    if (padded) {
        int y = p / WW, x = p % WW;
        dst[((size_t)(b*HID + c))*NP + (y+1)*WP + (x+1)] = tf32r(gl);
    } else {
        dst[idx] = gl;
    }
}

// ---------------- 6. head convs ----------------------------------------------------
__global__ void head_kernel(const float* __restrict__ h,
                            const float* __restrict__ wd, const float* __restrict__ bd,
                            const float* __restrict__ wc, const float* __restrict__ bc,
                            float* __restrict__ out) {
    __shared__ float s_in[8][10][34];
    __shared__ float s_w[8][9][4];
    int tid = threadIdx.x;
    int tx = tid & 31, ty = tid >> 5;
    int xbase = blockIdx.x*32, ybase = blockIdx.y*8, b = blockIdx.z;
    float a0 = 0.f, a1 = 0.f, a2 = 0.f;

    for (int ccn = 0; ccn < HID/8; ccn++) {
        int ic0 = ccn*8;
        for (int e = tid; e < 8*10*34; e += 256) {
            int c = e / 340, r = (e / 34) % 10, col = e % 34;
            int gy = ybase - 1 + r, gx = xbase - 1 + col;
            float v = 0.f;
            if (gy >= 0 && gy < HH && gx >= 0 && gx < WW)
                v = h[((size_t)(b*HID + ic0 + c)*HH + gy)*WW + gx];
            s_in[c][r][col] = v;
        }
        for (int e = tid; e < 8*9; e += 256) {
            int c = e / 9, kk = e % 9;
            s_w[c][kk][0] = wd[((size_t)(0*HID + ic0 + c))*9 + kk];
            s_w[c][kk][1] = wd[((size_t)(1*HID + ic0 + c))*9 + kk];
            s_w[c][kk][2] = wc[((size_t)(ic0 + c))*9 + kk];
        }
        __syncthreads();
        #pragma unroll
        for (int c = 0; c < 8; c++)
            #pragma unroll
            for (int ky = 0; ky < 3; ky++)
                #pragma unroll
                for (int kx = 0; kx < 3; kx++) {
                    float iv = s_in[c][ty+ky][tx+kx];
                    int kk = ky*3 + kx;
                    a0 += iv * s_w[c][kk][0];
                    a1 += iv * s_w[c][kk][1];
                    a2 += iv * s_w[c][kk][2];
                }
        __syncthreads();
    }
    int y = ybase + ty, x = xbase + tx;
    out[((size_t)(b*2 + 0)*HH + y)*WW + x] = tanhf(a0 + bd[0]);
    out[((size_t)(b*2 + 1)*HH + y)*WW + x] = tanhf(a1 + bd[1]);
    out[(size_t)BB*2*HW + ((size_t)b*HH + y)*WW + x] = 1.f / (1.f + expf(-(a2 + bc[0])));
}

// ---------------- launch ----------------------------------------------------------
extern "C" void kernel_launch(void* const* d_in, const int* in_sizes, int n_in,
                              void* d_out, int out_size) {
    const float* fa  = (const float*)d_in[0];
    const float* fb  = (const float*)d_in[1];
    const float* pf  = (const float*)d_in[2];
    const float* cm  = (const float*)d_in[3];
    const float* w1  = (const float*)d_in[4];
    const float* b1  = (const float*)d_in[5];
    const float* g1s = (const float*)d_in[6];
    const float* g1b = (const float*)d_in[7];
    const float* w2  = (const float*)d_in[8];
    const float* b2  = (const float*)d_in[9];
    const float* g2s = (const float*)d_in[10];
    const float* g2b = (const float*)d_in[11];
    const float* wd  = (const float*)d_in[12];
    const float* bd  = (const float*)d_in[13];
    const float* wc  = (const float*)d_in[14];
    const float* bc  = (const float*)d_in[15];
    float* out = (float*)d_out;

    float *p_xp_raw, *p_h1a_raw, *p_h1, *p_h2, *p_h2a, *p_wA1, *p_wA2;
    cudaGetSymbolAddress((void**)&p_xp_raw,  g_xp_raw);
    cudaGetSymbolAddress((void**)&p_h1a_raw, g_h1a_raw);
    cudaGetSymbolAddress((void**)&p_h1,  g_h1);
    cudaGetSymbolAddress((void**)&p_h2,  g_h2);
    cudaGetSymbolAddress((void**)&p_h2a, g_h2a);
    cudaGetSymbolAddress((void**)&p_wA1, g_wA1);
    cudaGetSymbolAddress((void**)&p_wA2, g_wA2);
    float* p_xp  = p_xp_raw  + SLACK;
    float* p_h1a = p_h1a_raw + SLACK;

    const int convSmem = (2*32*BST + 2*AFSZ) * 4;   // 174080 B
    const int corrSmem = (2*8*128 + 10*8*136) * 4;  // 51712 B
    static int attrSet = 0;
    if (!attrSet) {
        cudaFuncSetAttribute(conv_mma_kernel,
                             cudaFuncAttributeMaxDynamicSharedMemorySize, convSmem);
        cudaFuncSetAttribute(corr_part_kernel,
                             cudaFuncAttributeMaxDynamicSharedMemorySize, corrSmem);
        attrSet = 1;
    }

    prep_w_kernel<<<(NCH1*9*AFSZ + 255)/256, 256>>>(w1, w2);
    fill_warp_kernel<<<BB*HW/64, 256>>>(fa, fb, pf, cm, p_xp);
    corr_part_kernel<<<dim3(HH/2, BB, 2), dim3(32, 9), corrSmem>>>(fa);
    corr_combine_kernel<<<(BB*81*HW + 255)/256, 256>>>(p_xp);

    // conv1: K = 9 * 608
    conv_mma_kernel<<<dim3(NTILES, 1, BB), 256, convSmem>>>(p_xp, p_wA1, b1, p_h1, ICP1, NCH1);
    gn_stats_part<<<BB*GROUPS*8, 256>>>(p_h1);
    gn_stats_fin<<<1, 32>>>();
    gn_apply_gelu_kernel<<<(BB*HID*HW + 255)/256, 256>>>(p_h1, g1s, g1b, p_h1a, 1);

    // conv2: K = 9 * 128
    conv_mma_kernel<<<dim3(NTILES, 1, BB), 256, convSmem>>>(p_h1a, p_wA2, b2, p_h2, HID, NCH2);
    gn_stats_part<<<BB*GROUPS*8, 256>>>(p_h2);
    gn_stats_fin<<<1, 32>>>();
    gn_apply_gelu_kernel<<<(BB*HID*HW + 255)/256, 256>>>(p_h2, g2s, g2b, p_h2a, 0);

    head_kernel<<<dim3(WW/32, HH/8, BB), 256>>>(p_h2a, wd, bd, wc, bc, out);
}

// round 11
// speedup vs baseline: 1.0625x; 1.0625x over previous
#include <cuda_runtime.h>
#include <math.h>
#include <stdint.h>

#define BB 4
#define CC 256
#define HH 64
#define WW 128
#define HW (HH*WW)           // 8192
#define HID 128
#define IN_DIM 596
#define ICP1 608             // conv1 K-channels padded to /32
#define NCH1 19
#define NCH2 4
#define GROUPS 8
#define CPG (HID/GROUPS)     // 16

#define HP 66                // padded height (conv layout)
#define WP 130               // padded width  (conv layout)
#define NP (HP*WP)           // 8580 padded pixels
#define SLACK 512            // float slack both ends (B super-strip over-read)

#define BH 72                // corr-padded height (+-4)
#define BW 136               // corr-padded width  (+-4)
#define NB (BH*BW)           // 9792

#define TQ 256               // conv CTA N-tile (q pixels)
#define NTILES 34            // ceil(8580/256)
#define BST 520              // B super-strip stride (>=519, ==8 mod 32, 16B-mult)
#define AFSZ 5120            // packed A floats per (ch,tap): 4k8 * 2wm * 32lane * 20

// ---------------- scratch (device globals; zero-initialized) ----------------------
__device__ float g_xp_raw [(size_t)BB*ICP1*NP + 2*SLACK];  // padded conv1 input
__device__ float g_h1a_raw[(size_t)BB*HID *NP + 2*SLACK];  // padded conv2 input
__device__ float g_bwp [(size_t)BB*CC*NB];   // warped feat_b, 4-px zero pad (fp32)
__device__ float g_invna[BB*HW];
__device__ float g_invnbp[BB*NB];
__device__ float g_h1 [(size_t)BB*HID*HW];
__device__ float g_h2 [(size_t)BB*HID*HW];
__device__ float g_h2a[(size_t)BB*HID*HW];
__device__ float g_gnm[BB*GROUPS];
__device__ float g_gnr[BB*GROUPS];
__device__ double g_gnp[BB*GROUPS*8][2];
__device__ float g_wA1[(size_t)NCH1*9*AFSZ];  // fragment-packed conv1 weights
__device__ float g_wA2[(size_t)NCH2*9*AFSZ];

__device__ __forceinline__ float tf32r(float x) {
    uint32_t u;
    asm("cvt.rna.tf32.f32 %0, %1;" : "=r"(u) : "f"(x));
    return __uint_as_float(u);
}
__device__ __forceinline__ uint32_t s2u(const void* p) {
    return (uint32_t)__cvta_generic_to_shared(p);
}
__device__ __forceinline__ void cpa16(uint32_t s, const void* g) {
    asm volatile("cp.async.cg.shared.global [%0], [%1], 16;" :: "r"(s), "l"(g));
}
#define CP_COMMIT() asm volatile("cp.async.commit_group;" ::: "memory")
#define CP_WAIT0()  asm volatile("cp.async.wait_group 0;" ::: "memory")
#define CP_WAIT1()  asm volatile("cp.async.wait_group 1;" ::: "memory")

// ---------------- 0. weight prep: fragment-packed layout --------------------------
// Af[(ch,tap)][k8][wm][lane][20]: first 16 floats = af[mt 0..3][j 0..3] for that thread.
__global__ void prep_w_kernel(const float* __restrict__ w1,
                              const float* __restrict__ w2) {
    int i = blockIdx.x*blockDim.x + threadIdx.x;
    if (i < NCH1*9*AFSZ) {
        int bi = i / AFSZ, r = i % AFSZ;
        int t = r % 20, s = r / 20;
        int lane = s & 31, wmk = s >> 5;
        int wm = wmk & 1, k8 = wmk >> 1;
        float v = 0.f;
        if (t < 16) {
            int mt = t >> 2, j = t & 3;
            int tig = lane & 3, g = lane >> 2;
            int k  = k8*8 + tig + (j >> 1)*4;
            int oc = wm*64 + mt*16 + g + (j & 1)*8;
            int ch = bi / 9, tap = bi % 9;
            int ic = ch*32 + k;
            if (ic < IN_DIM) v = tf32r(w1[((size_t)oc*IN_DIM + ic)*9 + tap]);
        }
        g_wA1[i] = v;
    }
    if (i < NCH2*9*AFSZ) {
        int bi = i / AFSZ, r = i % AFSZ;
        int t = r % 20, s = r / 20;
        int lane = s & 31, wmk = s >> 5;
        int wm = wmk & 1, k8 = wmk >> 1;
        float v = 0.f;
        if (t < 16) {
            int mt = t >> 2, j = t & 3;
            int tig = lane & 3, g = lane >> 2;
            int k  = k8*8 + tig + (j >> 1)*4;
            int oc = wm*64 + mt*16 + g + (j & 1)*8;
            int ch = bi / 9, tap = bi % 9;
            int ic = ch*32 + k;
            v = tf32r(w2[((size_t)oc*HID + ic)*9 + tap]);
        }
        g_wA2[i] = v;
    }
}

// ---------------- 1. warp + concat fill + norms -----------------------------------
__global__ void fill_warp_kernel(const float* __restrict__ fa,
                                 const float* __restrict__ fb,
                                 const float* __restrict__ pf,
                                 const float* __restrict__ cm,
                                 float* __restrict__ xp) {
    __shared__ float sha[4][64], shb[4][64];
    int tid = threadIdx.x;
    int pxl = tid & 63, ck = tid >> 6;
    int gp = blockIdx.x*64 + pxl;
    int b = gp / HW, p = gp % HW;
    int y = p / WW, x = p % WW;
    int pq = (y+1)*WP + (x+1);
    int bq = (y+4)*BW + (x+4);

    float fx = pf[((size_t)(b*2+0))*HW + p];
    float fy = pf[((size_t)(b*2+1))*HW + p];
    float px = (float)x + fx;
    float py = (float)y + fy;
    float x0f = floorf(px), y0f = floorf(py);
    float wx = px - x0f,    wy = py - y0f;
    int x0 = (int)x0f, y0 = (int)y0f;
    int x1 = x0 + 1,   y1 = y0 + 1;
    float vx0 = (x0 >= 0 && x0 < WW) ? 1.f : 0.f;
    float vx1 = (x1 >= 0 && x1 < WW) ? 1.f : 0.f;
    float vy0 = (y0 >= 0 && y0 < HH) ? 1.f : 0.f;
    float vy1 = (y1 >= 0 && y1 < HH) ? 1.f : 0.f;
    int xc0 = min(max(x0,0),WW-1), xc1 = min(max(x1,0),WW-1);
    int yc0 = min(max(y0,0),HH-1), yc1 = min(max(y1,0),HH-1);
    float w00 = (1.f-wx)*(1.f-wy) * vx0*vy0;
    float w01 = wx*(1.f-wy)       * vx1*vy0;
    float w10 = (1.f-wx)*wy       * vx0*vy1;
    float w11 = wx*wy             * vx1*vy1;
    int i00 = yc0*WW + xc0, i01 = yc0*WW + xc1;
    int i10 = yc1*WW + xc0, i11 = yc1*WW + xc1;

    float sa = 0.f, sb = 0.f;
    float* xb = xp + (size_t)b*ICP1*NP;
    float* bw = g_bwp + (size_t)b*CC*NB;
    int c0 = ck*64;
    #pragma unroll 4
    for (int c = c0; c < c0+64; c++) {
        float a = fa[((size_t)(b*CC+c))*HW + p];
        xb[(size_t)c*NP + pq] = tf32r(a);
        sa += a*a;
        const float* fbp = fb + ((size_t)(b*CC+c))*HW;
        float wv = fbp[i00]*w00 + fbp[i01]*w01 + fbp[i10]*w10 + fbp[i11]*w11;
        xb[(size_t)(CC+c)*NP + pq] = tf32r(wv);
        bw[(size_t)c*NB + bq] = wv;
        sb += wv*wv;
    }
    sha[ck][pxl] = sa; shb[ck][pxl] = sb;
    __syncthreads();
    if (ck == 0) {
        float ta = sha[0][pxl]+sha[1][pxl]+sha[2][pxl]+sha[3][pxl];
        float tb = shb[0][pxl]+shb[1][pxl]+shb[2][pxl]+shb[3][pxl];
        g_invna[gp] = 1.f / fmaxf(sqrtf(ta), 1e-12f);
        g_invnbp[(size_t)b*NB + bq] = 1.f / fmaxf(sqrtf(tb), 1e-12f);
        xb[(size_t)512*NP + pq] = tf32r(fx);
        xb[(size_t)513*NP + pq] = tf32r(fy);
        xb[(size_t)514*NP + pq] = tf32r(cm[(size_t)b*HW + p]);
    }
}

// ---------------- 2. local correlation (81 offsets) — round-9 version -------------
__global__ void corr_kernel(const float* __restrict__ fa, float* __restrict__ xp) {
    __shared__ float sa[8][WW];
    __shared__ float sb[9][8][BW];
    int y = blockIdx.x, b = blockIdx.y;
    int xg = threadIdx.x, dyi = threadIdx.y;
    int tid = dyi*32 + xg;
    int xb0 = xg*4;

    float acc[4][9];
    #pragma unroll
    for (int j = 0; j < 4; j++)
        #pragma unroll
        for (int d = 0; d < 9; d++) acc[j][d] = 0.f;

    const float* fab = fa  + (size_t)b*CC*HW + (size_t)y*WW;
    const float* bwb = g_bwp + (size_t)b*CC*NB + (size_t)(y+dyi)*BW;

    for (int cc = 0; cc < CC/8; cc++) {
        int ic0 = cc*8;
        if (tid < 256) {
            int c = tid >> 5, f4 = tid & 31;
            *(float4*)&sa[c][f4*4] =
                *(const float4*)(fab + (size_t)(ic0 + c)*HW + f4*4);
        }
        #pragma unroll
        for (int c = 0; c < 8; c++) {
            const float4* src = (const float4*)(bwb + (size_t)(ic0 + c)*NB);
            *(float4*)&sb[dyi][c][xg*4] = src[xg];
            if (xg < 2)
                *(float4*)&sb[dyi][c][(32+xg)*4] = src[32+xg];
        }
        __syncthreads();
        #pragma unroll
        for (int c = 0; c < 8; c++) {
            float4 a4 = *(const float4*)&sa[c][xb0];
            float av[4] = {a4.x, a4.y, a4.z, a4.w};
            float4 b0 = *(const float4*)&sb[dyi][c][xb0];
            float4 b1 = *(const float4*)&sb[dyi][c][xb0+4];
            float4 b2 = *(const float4*)&sb[dyi][c][xb0+8];
            float bv[12] = {b0.x,b0.y,b0.z,b0.w, b1.x,b1.y,b1.z,b1.w, b2.x,b2.y,b2.z,b2.w};
            #pragma unroll
            for (int j = 0; j < 4; j++)
                #pragma unroll
                for (int d = 0; d < 9; d++)
                    acc[j][d] += av[j] * bv[j+d];
        }
        __syncthreads();
    }

    float ina[4];
    #pragma unroll
    for (int j = 0; j < 4; j++) ina[j] = g_invna[(size_t)b*HW + y*WW + xb0 + j];
    const float* inbr = g_invnbp + (size_t)b*NB + (size_t)(y+dyi)*BW;
    float inb[12];
    #pragma unroll
    for (int t = 0; t < 12; t++) inb[t] = inbr[xb0 + t];

    #pragma unroll
    for (int d = 0; d < 9; d++) {
        int ch = 515 + (8 - dyi)*9 + (8 - d);
        float* o = &xp[((size_t)(b*ICP1 + ch))*NP + (y+1)*WP + xb0 + 1];
        #pragma unroll
        for (int j = 0; j < 4; j++)
            o[j] = tf32r(acc[j][d] * ina[j] * inb[j+d]);
    }
}

// ---------------- 3. conv3x3 tf32 mma GEMM, A+B double-buffered -------------------
__global__ __launch_bounds__(256, 1)
void conv_mma_kernel(const float* __restrict__ xp,
                     const float* __restrict__ wA,
                     const float* __restrict__ bias,
                     float* __restrict__ out,
                     int ICp, int nChunks) {
    extern __shared__ float smem[];
    float* Bs0 = smem;                     // 32*520
    float* Bs1 = smem + 32*BST;
    float* As0 = smem + 2*32*BST;          // AFSZ
    float* As1 = As0 + AFSZ;

    int tid  = threadIdx.x;
    int warp = tid >> 5, lane = tid & 31;
    int g = lane >> 2, tig = lane & 3;
    int wm = warp & 1;
    int n0 = (warp >> 1) * 64;
    int q0 = blockIdx.x * TQ;
    int b  = blockIdx.z;

    float acc[4][8][4];
    #pragma unroll
    for (int mt = 0; mt < 4; mt++)
        #pragma unroll
        for (int nt = 0; nt < 8; nt++)
            #pragma unroll
            for (int i = 0; i < 4; i++) acc[mt][nt][i] = 0.f;

    const float* xpb = xp + (size_t)b*ICp*NP + q0 - 132;
    uint32_t asU[2] = {s2u(As0), s2u(As1)};
    uint32_t bsU[2] = {s2u(Bs0), s2u(Bs1)};

    auto stageB = [&](int s, int ch) {
        const float* src = xpb + (size_t)ch*32*NP;
        #pragma unroll
        for (int r = 0; r < 17; r++) {
            int e = tid + r*256;
            if (e < 32*(BST/4)) {
                int k = e / (BST/4), n4 = e - k*(BST/4);
                cpa16(bsU[s] + (uint32_t)(k*BST + n4*4)*4, src + (size_t)k*NP + n4*4);
            }
        }
    };
    auto stageA = [&](int s, int ch, int tap) {
        const float* src = wA + ((size_t)ch*9 + tap)*AFSZ;
        #pragma unroll
        for (int r = 0; r < 5; r++) {
            int e = tid + r*256;
            cpa16(asU[s] + (uint32_t)(e << 4), src + (e << 2));
        }
    };

    stageB(0, 0);
    stageA(0, 0, 0);
    CP_COMMIT();
    CP_WAIT0();
    __syncthreads();

    float* Acur = As0; float* Anxt = As1;
    float* Bcur = Bs0; float* Bnxt = Bs1;
    int aCur0 = 1, bCur0 = 1;

    for (int ch = 0; ch < nChunks; ch++) {
        bool moreCh = (ch + 1 < nChunks);
        for (int tap = 0; tap < 9; tap++) {
            bool lastAll = !moreCh && (tap == 8);
            bool bStageTap = (tap == 7) && moreCh;
            if (!lastAll) {
                int ntap = (tap == 8) ? 0 : tap + 1;
                int nch  = (tap == 8) ? ch + 1 : ch;
                stageA(aCur0 ? 1 : 0, nch, ntap);
                CP_COMMIT();
                if (bStageTap) {
                    stageB(bCur0 ? 1 : 0, ch + 1);
                    CP_COMMIT();
                }
            }
            int ky = tap / 3, kx = tap - ky*3;
            int boff = 132 + (ky-1)*WP + (kx-1);
            #pragma unroll
            for (int k8 = 0; k8 < 4; k8++) {
                int kb = k8*8;
                const float4* Ab = (const float4*)&Acur[(((k8<<1) | wm)*32 + lane)*20];
                uint32_t af[4][4];
                #pragma unroll
                for (int mt = 0; mt < 4; mt++) {
                    float4 av = Ab[mt];
                    af[mt][0] = __float_as_uint(av.x);
                    af[mt][1] = __float_as_uint(av.y);
                    af[mt][2] = __float_as_uint(av.z);
                    af[mt][3] = __float_as_uint(av.w);
                }
                const float* B0 = &Bcur[(kb+tig)*BST + boff];
                const float* B4 = B0 + 4*BST;
                #pragma unroll
                for (int nt = 0; nt < 8; nt++) {
                    int n = n0 + nt*8 + g;
                    uint32_t b0 = __float_as_uint(B0[n]);
                    uint32_t b1 = __float_as_uint(B4[n]);
                    #pragma unroll
                    for (int mt = 0; mt < 4; mt++) {
                        float* d = acc[mt][nt];
                        asm volatile(
                            "mma.sync.aligned.m16n8k8.row.col.f32.tf32.tf32.f32 "
                            "{%0,%1,%2,%3},{%4,%5,%6,%7},{%8,%9},{%0,%1,%2,%3};"
                            : "+f"(d[0]), "+f"(d[1]), "+f"(d[2]), "+f"(d[3])
                            : "r"(af[mt][0]), "r"(af[mt][1]), "r"(af[mt][2]), "r"(af[mt][3]),
                              "r"(b0), "r"(b1));
                    }
                }
            }
            if (!lastAll) {
                if (bStageTap) CP_WAIT1(); else CP_WAIT0();
                __syncthreads();
                { float* t = Acur; Acur = Anxt; Anxt = t; aCur0 ^= 1; }
                if (tap == 8) { float* t = Bcur; Bcur = Bnxt; Bnxt = t; bCur0 ^= 1; }
            }
        }
    }

    // epilogue
    #pragma unroll
    for (int mt = 0; mt < 4; mt++) {
        int ocA = wm*64 + mt*16 + g;
        int ocB = ocA + 8;
        float bvA = bias[ocA], bvB = bias[ocB];
        float* outA = out + ((size_t)(b*HID + ocA))*HW;
        float* outB = out + ((size_t)(b*HID + ocB))*HW;
        #pragma unroll
        for (int nt = 0; nt < 8; nt++) {
            int qb = q0 + n0 + nt*8 + tig*2;
            #pragma unroll
            for (int h = 0; h < 2; h++) {
                int q = qb + h;
                int yp = q / WP, xpx = q - yp*WP;
                if (yp >= 1 && yp <= HH && xpx >= 1 && xpx <= WW) {
                    int po = (yp-1)*WW + (xpx-1);
                    outA[po] = acc[mt][nt][h]   + bvA;
                    outB[po] = acc[mt][nt][2+h] + bvB;
                }
            }
        }
    }
}

// ---------------- 4. GroupNorm stats ----------------------------------------------
__global__ void gn_stats_part(const float* __restrict__ src) {
    int bg = blockIdx.x >> 3, part = blockIdx.x & 7;
    const float* p = src + (size_t)bg*CPG*HW + (size_t)part*(CPG*HW/8);
    const int n = CPG*HW/8;
    double s = 0.0, s2 = 0.0;
    for (int i = threadIdx.x; i < n; i += 256) {
        float v = p[i];
        s += v; s2 += (double)v*v;
    }
    __shared__ double sh[256], sh2[256];
    sh[threadIdx.x] = s; sh2[threadIdx.x] = s2;
    __syncthreads();
    for (int st = 128; st > 0; st >>= 1) {
        if (threadIdx.x < st) {
            sh[threadIdx.x]  += sh[threadIdx.x+st];
            sh2[threadIdx.x] += sh2[threadIdx.x+st];
        }
        __syncthreads();
    }
    if (threadIdx.x == 0) {
        g_gnp[blockIdx.x][0] = sh[0];
        g_gnp[blockIdx.x][1] = sh2[0];
    }
}
__global__ void gn_stats_fin() {
    int bg = threadIdx.x;
    if (bg >= BB*GROUPS) return;
    double s = 0.0, s2 = 0.0;
    for (int i = 0; i < 8; i++) { s += g_gnp[bg*8+i][0]; s2 += g_gnp[bg*8+i][1]; }
    const double n = (double)(CPG*HW);
    double m = s / n;
    double var = s2 / n - m*m;
    g_gnm[bg] = (float)m;
    g_gnr[bg] = rsqrtf((float)var + 1e-5f);
}

// ---------------- 5. GroupNorm apply + exact GELU ---------------------------------
__global__ void gn_apply_gelu_kernel(const float* __restrict__ src,
                                     const float* __restrict__ sc,
                                     const float* __restrict__ bi,
                                     float* __restrict__ dst,
                                     int padded) {
    int idx = blockIdx.x*blockDim.x + threadIdx.x;
    if (idx >= BB*HID*HW) return;
    int p = idx % HW;
    int c = (idx / HW) % HID;
    int b = idx / (HID*HW);
    int bg = b*GROUPS + c/CPG;
    float v = (src[idx] - g_gnm[bg]) * g_gnr[bg] * sc[c] + bi[c];
    float gl = 0.5f * v * (1.f + erff(v * 0.70710678118654752f));
    if (padded) {
        int y = p / WW, x = p % WW;
        dst[((size_t)(b*HID + c))*NP + (y+1)*WP + (x+1)] = tf32r(gl);
    } else {
        dst[idx] = gl;
    }
}

// ---------------- 6. head convs ----------------------------------------------------
__global__ void head_kernel(const float* __restrict__ h,
                            const float* __restrict__ wd, const float* __restrict__ bd,
                            const float* __restrict__ wc, const float* __restrict__ bc,
                            float* __restrict__ out) {
    __shared__ float s_in[8][10][34];
    __shared__ float s_w[8][9][4];
    int tid = threadIdx.x;
    int tx = tid & 31, ty = tid >> 5;
    int xbase = blockIdx.x*32, ybase = blockIdx.y*8, b = blockIdx.z;
    float a0 = 0.f, a1 = 0.f, a2 = 0.f;

    for (int ccn = 0; ccn < HID/8; ccn++) {
        int ic0 = ccn*8;
        for (int e = tid; e < 8*10*34; e += 256) {
            int c = e / 340, r = (e / 34) % 10, col = e % 34;
            int gy = ybase - 1 + r, gx = xbase - 1 + col;
            float v = 0.f;
            if (gy >= 0 && gy < HH && gx >= 0 && gx < WW)
                v = h[((size_t)(b*HID + ic0 + c)*HH + gy)*WW + gx];
            s_in[c][r][col] = v;
        }
        for (int e = tid; e < 8*9; e += 256) {
            int c = e / 9, kk = e % 9;
            s_w[c][kk][0] = wd[((size_t)(0*HID + ic0 + c))*9 + kk];
            s_w[c][kk][1] = wd[((size_t)(1*HID + ic0 + c))*9 + kk];
            s_w[c][kk][2] = wc[((size_t)(ic0 + c))*9 + kk];
        }
        __syncthreads();
        #pragma unroll
        for (int c = 0; c < 8; c++)
            #pragma unroll
            for (int ky = 0; ky < 3; ky++)
                #pragma unroll
                for (int kx = 0; kx < 3; kx++) {
                    float iv = s_in[c][ty+ky][tx+kx];
                    int kk = ky*3 + kx;
                    a0 += iv * s_w[c][kk][0];
                    a1 += iv * s_w[c][kk][1];
                    a2 += iv * s_w[c][kk][2];
                }
        __syncthreads();
    }
    int y = ybase + ty, x = xbase + tx;
    out[((size_t)(b*2 + 0)*HH + y)*WW + x] = tanhf(a0 + bd[0]);
    out[((size_t)(b*2 + 1)*HH + y)*WW + x] = tanhf(a1 + bd[1]);
    out[(size_t)BB*2*HW + ((size_t)b*HH + y)*WW + x] = 1.f / (1.f + expf(-(a2 + bc[0])));
}

// ---------------- launch ----------------------------------------------------------
extern "C" void kernel_launch(void* const* d_in, const int* in_sizes, int n_in,
                              void* d_out, int out_size) {
    const float* fa  = (const float*)d_in[0];
    const float* fb  = (const float*)d_in[1];
    const float* pf  = (const float*)d_in[2];
    const float* cm  = (const float*)d_in[3];
    const float* w1  = (const float*)d_in[4];
    const float* b1  = (const float*)d_in[5];
    const float* g1s = (const float*)d_in[6];
    const float* g1b = (const float*)d_in[7];
    const float* w2  = (const float*)d_in[8];
    const float* b2  = (const float*)d_in[9];
    const float* g2s = (const float*)d_in[10];
    const float* g2b = (const float*)d_in[11];
    const float* wd  = (const float*)d_in[12];
    const float* bd  = (const float*)d_in[13];
    const float* wc  = (const float*)d_in[14];
    const float* bc  = (const float*)d_in[15];
    float* out = (float*)d_out;

    float *p_xp_raw, *p_h1a_raw, *p_h1, *p_h2, *p_h2a, *p_wA1, *p_wA2;
    cudaGetSymbolAddress((void**)&p_xp_raw,  g_xp_raw);
    cudaGetSymbolAddress((void**)&p_h1a_raw, g_h1a_raw);
    cudaGetSymbolAddress((void**)&p_h1,  g_h1);
    cudaGetSymbolAddress((void**)&p_h2,  g_h2);
    cudaGetSymbolAddress((void**)&p_h2a, g_h2a);
    cudaGetSymbolAddress((void**)&p_wA1, g_wA1);
    cudaGetSymbolAddress((void**)&p_wA2, g_wA2);
    float* p_xp  = p_xp_raw  + SLACK;
    float* p_h1a = p_h1a_raw + SLACK;

    const int convSmem = (2*32*BST + 2*AFSZ) * 4;   // 174080 B
    static int attrSet = 0;
    if (!attrSet) {
        cudaFuncSetAttribute(conv_mma_kernel,
                             cudaFuncAttributeMaxDynamicSharedMemorySize, convSmem);
        attrSet = 1;
    }

    prep_w_kernel<<<(NCH1*9*AFSZ + 255)/256, 256>>>(w1, w2);
    fill_warp_kernel<<<BB*HW/64, 256>>>(fa, fb, pf, cm, p_xp);
    corr_kernel<<<dim3(HH, BB), dim3(32, 9)>>>(fa, p_xp);

    // conv1: K = 9 * 608
    conv_mma_kernel<<<dim3(NTILES, 1, BB), 256, convSmem>>>(p_xp, p_wA1, b1, p_h1, ICP1, NCH1);
    gn_stats_part<<<BB*GROUPS*8, 256>>>(p_h1);
    gn_stats_fin<<<1, 32>>>();
    gn_apply_gelu_kernel<<<(BB*HID*HW + 255)/256, 256>>>(p_h1, g1s, g1b, p_h1a, 1);

    // conv2: K = 9 * 128
    conv_mma_kernel<<<dim3(NTILES, 1, BB), 256, convSmem>>>(p_h1a, p_wA2, b2, p_h2, HID, NCH2);
    gn_stats_part<<<BB*GROUPS*8, 256>>>(p_h2);
    gn_stats_fin<<<1, 32>>>();
    gn_apply_gelu_kernel<<<(BB*HID*HW + 255)/256, 256>>>(p_h2, g2s, g2b, p_h2a, 0);

    head_kernel<<<dim3(WW/32, HH/8, BB), 256>>>(p_h2a, wd, bd, wc, bc, out);
}